// round 14
// baseline (speedup 1.0000x reference)
#include <cuda_runtime.h>
#include <cuda_fp16.h>
#include <cstdint>

// Problem constants
#define BATCH 2
#define SEQ   2048
#define DIM   1024
#define HEADS 16
#define HDIM  64
#define MROWS (BATCH * SEQ)          // 4096
#define BH    (BATCH * HEADS)        // 32

// Q projection scale: (1/sqrt(64)) * log2(e)  -> softmax done in 2^x domain
#define QSCALE 0.180336879f

// ---------------- scratch (half operand buffers) ----------------
__device__ __half g_Xh[(size_t)MROWS * DIM];
__device__ __half g_Wh[(size_t)4 * DIM * DIM];
__device__ __half g_Qh[(size_t)MROWS * DIM];
__device__ __half g_Kh[(size_t)MROWS * DIM];
__device__ __half g_Vh[(size_t)MROWS * DIM];
__device__ __half g_Oh[(size_t)MROWS * DIM];

// ---------------- helpers ----------------
__device__ __forceinline__ uint32_t f2h2(float lo, float hi) {
    __half2 h = __floats2half2_rn(lo, hi);
    return *(uint32_t*)&h;
}

__device__ __forceinline__ float ex2f(float x) {
    float y;
    asm("ex2.approx.f32 %0, %1;" : "=f"(y) : "f"(x));
    return y;
}

__device__ __forceinline__ void mma_f16(float c[4], const uint32_t a[4], const uint32_t b[2]) {
    asm volatile(
        "mma.sync.aligned.m16n8k16.row.col.f32.f16.f16.f32 "
        "{%0,%1,%2,%3}, {%4,%5,%6,%7}, {%8,%9}, {%0,%1,%2,%3};\n"
        : "+f"(c[0]), "+f"(c[1]), "+f"(c[2]), "+f"(c[3])
        : "r"(a[0]), "r"(a[1]), "r"(a[2]), "r"(a[3]), "r"(b[0]), "r"(b[1]));
}

__device__ __forceinline__ void ldsm4(uint32_t r[4], uint32_t addr) {
    asm volatile("ldmatrix.sync.aligned.m8n8.x4.shared.b16 {%0,%1,%2,%3}, [%4];"
        : "=r"(r[0]), "=r"(r[1]), "=r"(r[2]), "=r"(r[3]) : "r"(addr));
}

__device__ __forceinline__ void ldsm4t(uint32_t r[4], uint32_t addr) {
    asm volatile("ldmatrix.sync.aligned.m8n8.x4.trans.shared.b16 {%0,%1,%2,%3}, [%4];"
        : "=r"(r[0]), "=r"(r[1]), "=r"(r[2]), "=r"(r[3]) : "r"(addr));
}

__device__ __forceinline__ uint32_t smem_u32(const void* p) {
    uint32_t a;
    asm("{ .reg .u64 t; cvta.to.shared.u64 t, %1; cvt.u32.u64 %0, t; }" : "=r"(a) : "l"(p));
    return a;
}

#define CP_ASYNC16(dst, src) \
    asm volatile("cp.async.cg.shared.global [%0], [%1], 16;" :: "r"((uint32_t)(dst)), "l"(src) : "memory")
#define CP_COMMIT() asm volatile("cp.async.commit_group;" ::: "memory")
#define CP_WAIT(n)  asm volatile("cp.async.wait_group %0;" :: "n"(n) : "memory")

// ---------------- pre-pass: convert x and weights to half ----------------
__global__ void to_half_kernel(const float* __restrict__ x,
                               const float* __restrict__ wq, const float* __restrict__ wk,
                               const float* __restrict__ wv, const float* __restrict__ wo)
{
    const size_t i = (size_t)blockIdx.x * blockDim.x + threadIdx.x;   // float4 index, 2M total
    const float4* src;
    uint2* dst;
    if (i < (1u << 20)) {
        src = (const float4*)x + i;
        dst = (uint2*)g_Xh + i;
    } else {
        size_t j = i - (1u << 20);
        int w = (int)(j >> 18);
        const float* s = (w == 0) ? wq : ((w == 1) ? wk : ((w == 2) ? wv : wo));
        src = (const float4*)s + (j & 0x3FFFF);
        dst = (uint2*)g_Wh + j;
    }
    float4 v = *src;
    *dst = make_uint2(f2h2(v.x, v.y), f2h2(v.z, v.w));
}

// ---------------- fp16 GEMM: 128x64 tiles, occ-3, 2-stage cp.async ----------------
#define RSTR     144                  // row stride bytes (64 halfs + 8 pad)
#define GA_BYTES (128 * RSTR)         // A operand per stage = 18432
#define GB_BYTES (64 * RSTR)          // B operand per stage = 9216
#define GSTG     (GA_BYTES + GB_BYTES)  // 27648
#define G_SMEM   (2 * GSTG)           // 55296

template<bool QKV>
__global__ void __launch_bounds__(256, 3)
gemm_h(const __half* __restrict__ A, const __half* __restrict__ W,
       __half* __restrict__ C0h, __half* __restrict__ C1h, __half* __restrict__ C2h,
       float* __restrict__ Cf, const float* __restrict__ bias,
       const float* __restrict__ cosb, const float* __restrict__ sinb)
{
    extern __shared__ __align__(16) char sm[];
    const uint32_t sb = smem_u32(sm);

    const int z = blockIdx.z;
    const __half* B = W + ((size_t)(QKV ? z : 3) << 20);

    const int m0 = blockIdx.y * 128;
    const int n0 = blockIdx.x * 64;

    const int tid  = threadIdx.x;
    const int warp = tid >> 5;
    const int lane = tid & 31;
    const int g    = lane >> 2;
    const int t    = lane & 3;
    const int wm   = warp >> 1;          // 0..3 (m)
    const int wn   = warp & 1;           // 0..1 (n)

    // ldmatrix per-lane base offsets (bytes)
    const uint32_t aBase = sb + (uint32_t)((wm * 32 + ((lane >> 3) & 1) * 8 + (lane & 7)) * RSTR
                                           + (lane >> 4) * 16);
    const uint32_t bBase = sb + (uint32_t)GA_BYTES
                         + (uint32_t)((wn * 32 + ((lane >> 4) & 1) * 8 + (lane & 7)) * RSTR
                                      + ((lane >> 3) & 1) * 16);

    float acc[2][4][4] = {};

    const int NIT = DIM / 64;   // 16

    auto fill = [&](int tt) {
        const int k0 = tt * 64;
        const uint32_t stA = sb + (uint32_t)((tt & 1) * GSTG);
        const uint32_t stB = stA + (uint32_t)GA_BYTES;
        #pragma unroll
        for (int j = 0; j < 4; j++) {            // A: 128 rows x 8 chunks = 1024
            int id = tid + 256 * j;
            int row = id >> 3, ch = id & 7;
            CP_ASYNC16(stA + (uint32_t)(row * RSTR + ch * 16),
                       &A[(size_t)(m0 + row) * DIM + k0 + ch * 8]);
        }
        #pragma unroll
        for (int j = 0; j < 2; j++) {            // B: 64 rows x 8 chunks = 512
            int id = tid + 256 * j;
            int row = id >> 3, ch = id & 7;
            CP_ASYNC16(stB + (uint32_t)(row * RSTR + ch * 16),
                       &B[(size_t)(n0 + row) * DIM + k0 + ch * 8]);
        }
        CP_COMMIT();
    };

    fill(0);

    #pragma unroll 1
    for (int it = 0; it < NIT; it++) {
        CP_WAIT(0);                  // tile it landed
        __syncthreads();             // all warps done reading the other stage
        if (it + 1 < NIT)
            fill(it + 1);            // overlaps this tile's compute

        const uint32_t sOff = (uint32_t)((it & 1) * GSTG);
        const uint32_t aS = aBase + sOff;
        const uint32_t bS = bBase + sOff;

        #pragma unroll
        for (int ks = 0; ks < 4; ks++) {
            uint32_t af[2][4];
            #pragma unroll
            for (int mf = 0; mf < 2; mf++)
                ldsm4(af[mf], aS + (uint32_t)(mf * 16 * RSTR + ks * 32));
            uint32_t bf[4][2];
            #pragma unroll
            for (int p = 0; p < 2; p++) {
                uint32_t tmp[4];
                ldsm4(tmp, bS + (uint32_t)(p * 16 * RSTR + ks * 32));
                bf[2 * p][0]     = tmp[0]; bf[2 * p][1]     = tmp[1];
                bf[2 * p + 1][0] = tmp[2]; bf[2 * p + 1][1] = tmp[3];
            }
            #pragma unroll
            for (int mf = 0; mf < 2; mf++)
                #pragma unroll
                for (int nf = 0; nf < 4; nf++)
                    mma_f16(acc[mf][nf], af[mf], bf[nf]);
        }
    }

    // epilogue
    #pragma unroll
    for (int mf = 0; mf < 2; mf++) {
        #pragma unroll
        for (int nf = 0; nf < 4; nf++) {
            int r = m0 + wm * 32 + mf * 16 + g;
            int c = n0 + wn * 32 + nf * 8 + 2 * t;
            float v00 = acc[mf][nf][0], v01 = acc[mf][nf][1];
            float v10 = acc[mf][nf][2], v11 = acc[mf][nf][3];
            if (QKV) {
                __half* C = (z == 0) ? C0h : ((z == 1) ? C1h : C2h);
                if (z < 2) {   // RoPE on Q,K; fold (1/8)*log2e scale into Q
                    int i  = (c & 63) >> 1;
                    int nA = r & 2047, nB = (r + 8) & 2047;
                    float cA = cosb[nA * 32 + i], sA = sinb[nA * 32 + i];
                    float cB = cosb[nB * 32 + i], sB = sinb[nB * 32 + i];
                    float o00 = v00 * cA - v01 * sA, o01 = v00 * sA + v01 * cA;
                    float o10 = v10 * cB - v11 * sB, o11 = v10 * sB + v11 * cB;
                    if (z == 0) { o00 *= QSCALE; o01 *= QSCALE; o10 *= QSCALE; o11 *= QSCALE; }
                    v00 = o00; v01 = o01; v10 = o10; v11 = o11;
                }
                *(uint32_t*)&C[(size_t)r       * DIM + c] = f2h2(v00, v01);
                *(uint32_t*)&C[(size_t)(r + 8) * DIM + c] = f2h2(v10, v11);
            } else {
                float b0 = bias[c], b1 = bias[c + 1];
                *(float2*)&Cf[(size_t)r       * DIM + c] = make_float2(v00 + b0, v01 + b1);
                *(float2*)&Cf[(size_t)(r + 8) * DIM + c] = make_float2(v10 + b0, v11 + b1);
            }
        }
    }
}

// ---------------- fp16 fused flash attention, double-buffered K/V ----------------
// Softmax in 2^x domain (log2e folded into Q); l accumulated via all-ones B-fragment mma.
#define FA_OPB  18432                 // one K or V operand (128 x 144B)
#define FA_Q    0
#define FA_KV   18432
#define FA_STG  36864
#define FA_SMEM (18432 + 2 * 36864)   // 92160

__global__ void __launch_bounds__(256, 2)
flash_attn(const __half* __restrict__ Q, const __half* __restrict__ K,
           const __half* __restrict__ V, __half* __restrict__ O)
{
    extern __shared__ __align__(16) char sm[];
    const uint32_t sb = smem_u32(sm);

    const int bh = blockIdx.y;
    const int b  = bh >> 4;
    const int h  = bh & 15;
    const int q0 = blockIdx.x * 128;

    const int tid  = threadIdx.x;
    const int warp = tid >> 5;
    const int lane = tid & 31;
    const int g    = lane >> 2;
    const int t    = lane & 3;
    const int wrow = warp * 16;

    const size_t hoff = (size_t)h * HDIM;
    const size_t tok0 = (size_t)b * SEQ;

    int crow[4], cch[4];
    #pragma unroll
    for (int j = 0; j < 4; j++) {
        int id = tid + 256 * j;
        crow[j] = id >> 3;
        cch[j]  = id & 7;
    }

    const uint32_t qAddr = sb + FA_Q + (uint32_t)((wrow + ((lane >> 3) & 1) * 8 + (lane & 7)) * RSTR
                                                  + (lane >> 4) * 16);
    const uint32_t kBase = sb + FA_KV + (uint32_t)((((lane >> 4) & 1) * 8 + (lane & 7)) * RSTR
                                                   + ((lane >> 3) & 1) * 16);
    const uint32_t vBase = sb + FA_KV + (uint32_t)FA_OPB
                         + (uint32_t)((((lane >> 3) & 1) * 8 + (lane & 7)) * RSTR
                                      + ((lane >> 4) & 1) * 16);

    auto fillKV = [&](int jt, int st) {
        const int j0 = jt * 128;
        const uint32_t stK = sb + FA_KV + (uint32_t)(st * FA_STG);
        const uint32_t stV = stK + (uint32_t)FA_OPB;
        #pragma unroll
        for (int j = 0; j < 4; j++) {
            CP_ASYNC16(stK + (uint32_t)(crow[j] * RSTR + cch[j] * 16),
                       &K[(tok0 + j0 + crow[j]) * DIM + hoff + cch[j] * 8]);
            CP_ASYNC16(stV + (uint32_t)(crow[j] * RSTR + cch[j] * 16),
                       &V[(tok0 + j0 + crow[j]) * DIM + hoff + cch[j] * 8]);
        }
        CP_COMMIT();
    };

    // prologue
    #pragma unroll
    for (int j = 0; j < 4; j++)
        CP_ASYNC16(sb + FA_Q + (uint32_t)(crow[j] * RSTR + cch[j] * 16),
                   &Q[(tok0 + q0 + crow[j]) * DIM + hoff + cch[j] * 8]);
    CP_COMMIT();
    fillKV(0, 0);

    float m0 = -1e30f, m1 = -1e30f;
    float oacc[8][4] = {};
    float lacc[4] = {};              // l via ones-column mma: lacc[0]=l0 rows, lacc[2]=l1 rows
    const uint32_t bones[2] = {0x3C003C00u, 0x3C003C00u};   // all-ones fp16 B fragment
    uint32_t qf[4][4];

    #pragma unroll 1
    for (int it = 0; it < SEQ / 128; it++) {
        CP_WAIT(0);
        __syncthreads();
        if (it == 0) {
            #pragma unroll
            for (int ks = 0; ks < 4; ks++)
                ldsm4(qf[ks], qAddr + (uint32_t)(ks * 32));
        }
        if (it + 1 < SEQ / 128)
            fillKV(it + 1, (it + 1) & 1);

        const uint32_t sOff = (uint32_t)((it & 1) * FA_STG);
        const uint32_t kS = kBase + sOff;
        const uint32_t vS = vBase + sOff;

        // ---- S = Q @ K^T (Q pre-scaled by (1/8)*log2e) ----
        float sacc[16][4];
        #pragma unroll
        for (int nf = 0; nf < 16; nf++)
            #pragma unroll
            for (int r = 0; r < 4; r++) sacc[nf][r] = 0.f;

        #pragma unroll
        for (int ks = 0; ks < 4; ks++) {
            #pragma unroll
            for (int p = 0; p < 8; p++) {
                uint32_t tmp[4];
                ldsm4(tmp, kS + (uint32_t)(p * 16 * RSTR + ks * 32));
                uint32_t b0[2] = {tmp[0], tmp[1]};
                uint32_t b1[2] = {tmp[2], tmp[3]};
                mma_f16(sacc[2 * p],     qf[ks], b0);
                mma_f16(sacc[2 * p + 1], qf[ks], b1);
            }
        }

        // ---- online softmax (2^x domain) ----
        float tm0 = -1e30f, tm1 = -1e30f;
        #pragma unroll
        for (int nf = 0; nf < 16; nf++) {
            tm0 = fmaxf(tm0, fmaxf(sacc[nf][0], sacc[nf][1]));
            tm1 = fmaxf(tm1, fmaxf(sacc[nf][2], sacc[nf][3]));
        }
        tm0 = fmaxf(tm0, __shfl_xor_sync(0xffffffffu, tm0, 1));
        tm0 = fmaxf(tm0, __shfl_xor_sync(0xffffffffu, tm0, 2));
        tm1 = fmaxf(tm1, __shfl_xor_sync(0xffffffffu, tm1, 1));
        tm1 = fmaxf(tm1, __shfl_xor_sync(0xffffffffu, tm1, 2));

        float nm0 = fmaxf(m0, tm0), nm1 = fmaxf(m1, tm1);
        float al0 = ex2f(m0 - nm0), al1 = ex2f(m1 - nm1);
        m0 = nm0; m1 = nm1;

        uint32_t ph[16][2];          // half2-packed P = 2^(s-m), PV A-fragment layout
        #pragma unroll
        for (int nf = 0; nf < 16; nf++) {
            float e0 = ex2f(sacc[nf][0] - m0);
            float e1 = ex2f(sacc[nf][1] - m0);
            float e2 = ex2f(sacc[nf][2] - m1);
            float e3 = ex2f(sacc[nf][3] - m1);
            ph[nf][0] = f2h2(e0, e1);
            ph[nf][1] = f2h2(e2, e3);
        }

        lacc[0] *= al0; lacc[1] *= al0;
        lacc[2] *= al1; lacc[3] *= al1;
        #pragma unroll
        for (int nf = 0; nf < 8; nf++) {
            oacc[nf][0] *= al0; oacc[nf][1] *= al0;
            oacc[nf][2] *= al1; oacc[nf][3] *= al1;
        }

        // ---- O += P @ V ; l += P @ ones ----
        #pragma unroll
        for (int ks = 0; ks < 8; ks++) {
            uint32_t a[4] = {ph[2 * ks][0], ph[2 * ks][1], ph[2 * ks + 1][0], ph[2 * ks + 1][1]};
            const uint32_t vk = vS + (uint32_t)(ks * 16 * RSTR);
            #pragma unroll
            for (int dt = 0; dt < 4; dt++) {
                uint32_t tmp[4];
                ldsm4t(tmp, vk + (uint32_t)(dt * 32));
                uint32_t b0[2] = {tmp[0], tmp[1]};
                uint32_t b1[2] = {tmp[2], tmp[3]};
                mma_f16(oacc[2 * dt],     a, b0);
                mma_f16(oacc[2 * dt + 1], a, b1);
            }
            mma_f16(lacc, a, bones);
        }
    }

    // ---- finalize ----
    const float inv0 = 1.f / lacc[0], inv1 = 1.f / lacc[2];
    #pragma unroll
    for (int nf = 0; nf < 8; nf++) {
        int r0 = q0 + wrow + g;
        int c  = nf * 8 + 2 * t;
        *(uint32_t*)&O[(tok0 + r0) * DIM + hoff + c]       = f2h2(oacc[nf][0] * inv0, oacc[nf][1] * inv0);
        *(uint32_t*)&O[(tok0 + r0 + 8) * DIM + hoff + c]   = f2h2(oacc[nf][2] * inv1, oacc[nf][3] * inv1);
    }
}

// ---------------- launch ----------------
extern "C" void kernel_launch(void* const* d_in, const int* in_sizes, int n_in,
                              void* d_out, int out_size)
{
    const float* x   = (const float*)d_in[0];
    const float* fc  = (const float*)d_in[1];
    const float* fs  = (const float*)d_in[2];
    const float* Wq  = (const float*)d_in[3];
    const float* Wk  = (const float*)d_in[4];
    const float* Wv  = (const float*)d_in[5];
    const float* Wo  = (const float*)d_in[6];
    const float* bo  = (const float*)d_in[7];
    float* out = (float*)d_out;

    __half *Xh, *Wh, *Qh, *Kh, *Vh, *Oh;
    cudaGetSymbolAddress((void**)&Xh, g_Xh);
    cudaGetSymbolAddress((void**)&Wh, g_Wh);
    cudaGetSymbolAddress((void**)&Qh, g_Qh);
    cudaGetSymbolAddress((void**)&Kh, g_Kh);
    cudaGetSymbolAddress((void**)&Vh, g_Vh);
    cudaGetSymbolAddress((void**)&Oh, g_Oh);

    // 0) convert inputs to half
    to_half_kernel<<<8192, 256>>>(x, Wq, Wk, Wv, Wo);

    // 1) fused QKV projections + RoPE (+QSCALE on Q) epilogue
    cudaFuncSetAttribute(gemm_h<true>,  cudaFuncAttributeMaxDynamicSharedMemorySize, G_SMEM);
    cudaFuncSetAttribute(gemm_h<false>, cudaFuncAttributeMaxDynamicSharedMemorySize, G_SMEM);
    dim3 gQKV(DIM / 64, MROWS / 128, 3);     // (16, 32, 3)
    gemm_h<true><<<gQKV, 256, G_SMEM>>>(Xh, Wh, Qh, Kh, Vh, nullptr, nullptr, fc, fs);

    // 2) fused attention (writes half O)
    cudaFuncSetAttribute(flash_attn, cudaFuncAttributeMaxDynamicSharedMemorySize, FA_SMEM);
    dim3 gFA(SEQ / 128, BH, 1);
    flash_attn<<<gFA, 256, FA_SMEM>>>(Qh, Kh, Vh, Oh);

    // 3) out = O @ Wo^T + bo
    dim3 gOut(DIM / 64, MROWS / 128, 1);     // (16, 32, 1)
    gemm_h<false><<<gOut, 256, G_SMEM>>>(Oh, Wh, nullptr, nullptr, nullptr, out, bo, nullptr, nullptr);
}

// round 15
// speedup vs baseline: 1.0581x; 1.0581x over previous
#include <cuda_runtime.h>
#include <cuda_fp16.h>
#include <cstdint>

// Problem constants
#define BATCH 2
#define SEQ   2048
#define DIM   1024
#define HEADS 16
#define HDIM  64
#define MROWS (BATCH * SEQ)          // 4096
#define BH    (BATCH * HEADS)        // 32

// Q projection scale: (1/sqrt(64)) * log2(e)  -> softmax done in 2^x domain
#define QSCALE 0.180336879f

// ---------------- scratch (half operand buffers) ----------------
__device__ __half g_Xh[(size_t)MROWS * DIM];
__device__ __half g_Wh[(size_t)4 * DIM * DIM];
__device__ __half g_Qh[(size_t)MROWS * DIM];
__device__ __half g_Kh[(size_t)MROWS * DIM];
__device__ __half g_Vh[(size_t)MROWS * DIM];
__device__ __half g_Oh[(size_t)MROWS * DIM];

// ---------------- helpers ----------------
__device__ __forceinline__ uint32_t f2h2(float lo, float hi) {
    __half2 h = __floats2half2_rn(lo, hi);
    return *(uint32_t*)&h;
}

__device__ __forceinline__ float ex2f(float x) {
    float y;
    asm("ex2.approx.f32 %0, %1;" : "=f"(y) : "f"(x));
    return y;
}

__device__ __forceinline__ void mma_f16(float c[4], const uint32_t a[4], const uint32_t b[2]) {
    asm volatile(
        "mma.sync.aligned.m16n8k16.row.col.f32.f16.f16.f32 "
        "{%0,%1,%2,%3}, {%4,%5,%6,%7}, {%8,%9}, {%0,%1,%2,%3};\n"
        : "+f"(c[0]), "+f"(c[1]), "+f"(c[2]), "+f"(c[3])
        : "r"(a[0]), "r"(a[1]), "r"(a[2]), "r"(a[3]), "r"(b[0]), "r"(b[1]));
}

__device__ __forceinline__ void ldsm4(uint32_t r[4], uint32_t addr) {
    asm volatile("ldmatrix.sync.aligned.m8n8.x4.shared.b16 {%0,%1,%2,%3}, [%4];"
        : "=r"(r[0]), "=r"(r[1]), "=r"(r[2]), "=r"(r[3]) : "r"(addr));
}

__device__ __forceinline__ void ldsm4t(uint32_t r[4], uint32_t addr) {
    asm volatile("ldmatrix.sync.aligned.m8n8.x4.trans.shared.b16 {%0,%1,%2,%3}, [%4];"
        : "=r"(r[0]), "=r"(r[1]), "=r"(r[2]), "=r"(r[3]) : "r"(addr));
}

__device__ __forceinline__ uint32_t smem_u32(const void* p) {
    uint32_t a;
    asm("{ .reg .u64 t; cvta.to.shared.u64 t, %1; cvt.u32.u64 %0, t; }" : "=r"(a) : "l"(p));
    return a;
}

#define CP_ASYNC16(dst, src) \
    asm volatile("cp.async.cg.shared.global [%0], [%1], 16;" :: "r"((uint32_t)(dst)), "l"(src) : "memory")
#define CP_COMMIT() asm volatile("cp.async.commit_group;" ::: "memory")
#define CP_WAIT(n)  asm volatile("cp.async.wait_group %0;" :: "n"(n) : "memory")

// ---------------- pre-pass: convert x and weights to half ----------------
__global__ void to_half_kernel(const float* __restrict__ x,
                               const float* __restrict__ wq, const float* __restrict__ wk,
                               const float* __restrict__ wv, const float* __restrict__ wo)
{
    const size_t i = (size_t)blockIdx.x * blockDim.x + threadIdx.x;   // float4 index, 2M total
    const float4* src;
    uint2* dst;
    if (i < (1u << 20)) {
        src = (const float4*)x + i;
        dst = (uint2*)g_Xh + i;
    } else {
        size_t j = i - (1u << 20);
        int w = (int)(j >> 18);
        const float* s = (w == 0) ? wq : ((w == 1) ? wk : ((w == 2) ? wv : wo));
        src = (const float4*)s + (j & 0x3FFFF);
        dst = (uint2*)g_Wh + j;
    }
    float4 v = *src;
    *dst = make_uint2(f2h2(v.x, v.y), f2h2(v.z, v.w));
}

// ---------------- fp16 ldmatrix + cp.async GEMM, 3-stage pipeline (R13 config) ----------------
#define RSTR   144                    // row stride bytes (64 halfs + 8 pad)
#define OPB    (128 * RSTR)           // bytes per operand per stage = 18432
#define STGB   (2 * OPB)              // bytes per stage             = 36864
#define G_SMEM (3 * STGB)             // 110592

template<bool QKV>
__global__ void __launch_bounds__(256, 2)
gemm_h(const __half* __restrict__ A, const __half* __restrict__ W,
       __half* __restrict__ C0h, __half* __restrict__ C1h, __half* __restrict__ C2h,
       float* __restrict__ Cf, const float* __restrict__ bias,
       const float* __restrict__ cosb, const float* __restrict__ sinb)
{
    extern __shared__ __align__(16) char sm[];
    const uint32_t sb = smem_u32(sm);

    const int z = blockIdx.z;
    const __half* B = W + ((size_t)(QKV ? z : 3) << 20);

    const int m0 = blockIdx.y * 128;
    const int n0 = blockIdx.x * 128;

    const int tid  = threadIdx.x;
    const int warp = tid >> 5;
    const int lane = tid & 31;
    const int g    = lane >> 2;
    const int t    = lane & 3;
    const int wm   = warp >> 2;          // 0..1
    const int wn   = warp & 3;           // 0..3

    int crow[4], cch[4];
    #pragma unroll
    for (int j = 0; j < 4; j++) {
        int id = tid + 256 * j;          // 0..1023
        crow[j] = id >> 3;
        cch[j]  = id & 7;
    }

    const uint32_t aBase = sb + (uint32_t)((wm * 64 + ((lane >> 3) & 1) * 8 + (lane & 7)) * RSTR
                                           + (lane >> 4) * 16);
    const uint32_t bBase = sb + (uint32_t)OPB
                         + (uint32_t)((wn * 32 + ((lane >> 4) & 1) * 8 + (lane & 7)) * RSTR
                                      + ((lane >> 3) & 1) * 16);

    float acc[4][4][4] = {};

    const int NIT = DIM / 64;   // 16

    auto fill = [&](int tt, int st) {
        if (tt < NIT) {
            const int k0 = tt * 64;
            const uint32_t stA = sb + (uint32_t)(st * STGB);
            const uint32_t stB = stA + (uint32_t)OPB;
            #pragma unroll
            for (int j = 0; j < 4; j++) {
                CP_ASYNC16(stA + (uint32_t)(crow[j] * RSTR + cch[j] * 16),
                           &A[(size_t)(m0 + crow[j]) * DIM + k0 + cch[j] * 8]);
                CP_ASYNC16(stB + (uint32_t)(crow[j] * RSTR + cch[j] * 16),
                           &B[(size_t)(n0 + crow[j]) * DIM + k0 + cch[j] * 8]);
            }
        }
        CP_COMMIT();
    };

    fill(0, 0);
    fill(1, 1);

    int s = 0;
    #pragma unroll 1
    for (int it = 0; it < NIT; it++) {
        CP_WAIT(1);
        __syncthreads();
        {
            int s2 = s + 2; if (s2 >= 3) s2 -= 3;
            fill(it + 2, s2);
        }

        const uint32_t sOff = (uint32_t)(s * STGB);
        const uint32_t aS = aBase + sOff;
        const uint32_t bS = bBase + sOff;

        #pragma unroll
        for (int ks = 0; ks < 4; ks++) {
            uint32_t af[4][4];
            #pragma unroll
            for (int mf = 0; mf < 4; mf++)
                ldsm4(af[mf], aS + (uint32_t)(mf * 16 * RSTR + ks * 32));
            uint32_t bf[4][2];
            #pragma unroll
            for (int p = 0; p < 2; p++) {
                uint32_t tmp[4];
                ldsm4(tmp, bS + (uint32_t)(p * 16 * RSTR + ks * 32));
                bf[2 * p][0]     = tmp[0]; bf[2 * p][1]     = tmp[1];
                bf[2 * p + 1][0] = tmp[2]; bf[2 * p + 1][1] = tmp[3];
            }
            #pragma unroll
            for (int mf = 0; mf < 4; mf++)
                #pragma unroll
                for (int nf = 0; nf < 4; nf++)
                    mma_f16(acc[mf][nf], af[mf], bf[nf]);
        }
        s = (s == 2) ? 0 : s + 1;
    }

    // epilogue
    #pragma unroll
    for (int mf = 0; mf < 4; mf++) {
        #pragma unroll
        for (int nf = 0; nf < 4; nf++) {
            int r = m0 + wm * 64 + mf * 16 + g;
            int c = n0 + wn * 32 + nf * 8 + 2 * t;
            float v00 = acc[mf][nf][0], v01 = acc[mf][nf][1];
            float v10 = acc[mf][nf][2], v11 = acc[mf][nf][3];
            if (QKV) {
                __half* C = (z == 0) ? C0h : ((z == 1) ? C1h : C2h);
                if (z < 2) {   // RoPE on Q,K; fold (1/8)*log2e scale into Q
                    int i  = (c & 63) >> 1;
                    int nA = r & 2047, nB = (r + 8) & 2047;
                    float cA = cosb[nA * 32 + i], sA = sinb[nA * 32 + i];
                    float cB = cosb[nB * 32 + i], sB = sinb[nB * 32 + i];
                    float o00 = v00 * cA - v01 * sA, o01 = v00 * sA + v01 * cA;
                    float o10 = v10 * cB - v11 * sB, o11 = v10 * sB + v11 * cB;
                    if (z == 0) { o00 *= QSCALE; o01 *= QSCALE; o10 *= QSCALE; o11 *= QSCALE; }
                    v00 = o00; v01 = o01; v10 = o10; v11 = o11;
                }
                *(uint32_t*)&C[(size_t)r       * DIM + c] = f2h2(v00, v01);
                *(uint32_t*)&C[(size_t)(r + 8) * DIM + c] = f2h2(v10, v11);
            } else {
                float b0 = bias[c], b1 = bias[c + 1];
                *(float2*)&Cf[(size_t)r       * DIM + c] = make_float2(v00 + b0, v01 + b1);
                *(float2*)&Cf[(size_t)(r + 8) * DIM + c] = make_float2(v10 + b0, v11 + b1);
            }
        }
    }
}

// ---------------- fp16 fused flash attention, double-buffered K/V ----------------
// Softmax in 2^x domain; l via ones-mma. Prefetch of next K/V issued AFTER the
// S-phase (out of the LDSM-dense window), still overlapping softmax + PV.
#define FA_OPB  18432
#define FA_Q    0
#define FA_KV   18432
#define FA_STG  36864
#define FA_SMEM (18432 + 2 * 36864)   // 92160

__global__ void __launch_bounds__(256, 2)
flash_attn(const __half* __restrict__ Q, const __half* __restrict__ K,
           const __half* __restrict__ V, __half* __restrict__ O)
{
    extern __shared__ __align__(16) char sm[];
    const uint32_t sb = smem_u32(sm);

    const int bh = blockIdx.y;
    const int b  = bh >> 4;
    const int h  = bh & 15;
    const int q0 = blockIdx.x * 128;

    const int tid  = threadIdx.x;
    const int warp = tid >> 5;
    const int lane = tid & 31;
    const int g    = lane >> 2;
    const int t    = lane & 3;
    const int wrow = warp * 16;

    const size_t hoff = (size_t)h * HDIM;
    const size_t tok0 = (size_t)b * SEQ;

    int crow[4], cch[4];
    #pragma unroll
    for (int j = 0; j < 4; j++) {
        int id = tid + 256 * j;
        crow[j] = id >> 3;
        cch[j]  = id & 7;
    }

    const uint32_t qAddr = sb + FA_Q + (uint32_t)((wrow + ((lane >> 3) & 1) * 8 + (lane & 7)) * RSTR
                                                  + (lane >> 4) * 16);
    const uint32_t kBase = sb + FA_KV + (uint32_t)((((lane >> 4) & 1) * 8 + (lane & 7)) * RSTR
                                                   + ((lane >> 3) & 1) * 16);
    const uint32_t vBase = sb + FA_KV + (uint32_t)FA_OPB
                         + (uint32_t)((((lane >> 3) & 1) * 8 + (lane & 7)) * RSTR
                                      + ((lane >> 4) & 1) * 16);

    auto fillKV = [&](int jt, int st) {
        const int j0 = jt * 128;
        const uint32_t stK = sb + FA_KV + (uint32_t)(st * FA_STG);
        const uint32_t stV = stK + (uint32_t)FA_OPB;
        #pragma unroll
        for (int j = 0; j < 4; j++) {
            CP_ASYNC16(stK + (uint32_t)(crow[j] * RSTR + cch[j] * 16),
                       &K[(tok0 + j0 + crow[j]) * DIM + hoff + cch[j] * 8]);
            CP_ASYNC16(stV + (uint32_t)(crow[j] * RSTR + cch[j] * 16),
                       &V[(tok0 + j0 + crow[j]) * DIM + hoff + cch[j] * 8]);
        }
        CP_COMMIT();
    };

    // prologue
    #pragma unroll
    for (int j = 0; j < 4; j++)
        CP_ASYNC16(sb + FA_Q + (uint32_t)(crow[j] * RSTR + cch[j] * 16),
                   &Q[(tok0 + q0 + crow[j]) * DIM + hoff + cch[j] * 8]);
    CP_COMMIT();
    fillKV(0, 0);

    float m0 = -1e30f, m1 = -1e30f;
    float oacc[8][4] = {};
    float lacc[4] = {};              // l via ones-column mma: lacc[0]=l0 rows, lacc[2]=l1 rows
    const uint32_t bones[2] = {0x3C003C00u, 0x3C003C00u};   // all-ones fp16 B fragment
    uint32_t qf[4][4];

    #pragma unroll 1
    for (int it = 0; it < SEQ / 128; it++) {
        CP_WAIT(0);
        __syncthreads();
        if (it == 0) {
            #pragma unroll
            for (int ks = 0; ks < 4; ks++)
                ldsm4(qf[ks], qAddr + (uint32_t)(ks * 32));
        }

        const uint32_t sOff = (uint32_t)((it & 1) * FA_STG);
        const uint32_t kS = kBase + sOff;
        const uint32_t vS = vBase + sOff;

        // ---- S = Q @ K^T (Q pre-scaled by (1/8)*log2e) ----
        float sacc[16][4];
        #pragma unroll
        for (int nf = 0; nf < 16; nf++)
            #pragma unroll
            for (int r = 0; r < 4; r++) sacc[nf][r] = 0.f;

        #pragma unroll
        for (int ks = 0; ks < 4; ks++) {
            #pragma unroll
            for (int p = 0; p < 8; p++) {
                uint32_t tmp[4];
                ldsm4(tmp, kS + (uint32_t)(p * 16 * RSTR + ks * 32));
                uint32_t b0[2] = {tmp[0], tmp[1]};
                uint32_t b1[2] = {tmp[2], tmp[3]};
                mma_f16(sacc[2 * p],     qf[ks], b0);
                mma_f16(sacc[2 * p + 1], qf[ks], b1);
            }
        }

        // prefetch next K/V AFTER the S-phase LDSM burst; overlaps softmax + PV
        if (it + 1 < SEQ / 128)
            fillKV(it + 1, (it + 1) & 1);

        // ---- online softmax (2^x domain) ----
        float tm0 = -1e30f, tm1 = -1e30f;
        #pragma unroll
        for (int nf = 0; nf < 16; nf++) {
            tm0 = fmaxf(tm0, fmaxf(sacc[nf][0], sacc[nf][1]));
            tm1 = fmaxf(tm1, fmaxf(sacc[nf][2], sacc[nf][3]));
        }
        tm0 = fmaxf(tm0, __shfl_xor_sync(0xffffffffu, tm0, 1));
        tm0 = fmaxf(tm0, __shfl_xor_sync(0xffffffffu, tm0, 2));
        tm1 = fmaxf(tm1, __shfl_xor_sync(0xffffffffu, tm1, 1));
        tm1 = fmaxf(tm1, __shfl_xor_sync(0xffffffffu, tm1, 2));

        float nm0 = fmaxf(m0, tm0), nm1 = fmaxf(m1, tm1);
        float al0 = ex2f(m0 - nm0), al1 = ex2f(m1 - nm1);
        m0 = nm0; m1 = nm1;

        uint32_t ph[16][2];          // half2-packed P = 2^(s-m), PV A-fragment layout
        #pragma unroll
        for (int nf = 0; nf < 16; nf++) {
            float e0 = ex2f(sacc[nf][0] - m0);
            float e1 = ex2f(sacc[nf][1] - m0);
            float e2 = ex2f(sacc[nf][2] - m1);
            float e3 = ex2f(sacc[nf][3] - m1);
            ph[nf][0] = f2h2(e0, e1);
            ph[nf][1] = f2h2(e2, e3);
        }

        lacc[0] *= al0; lacc[1] *= al0;
        lacc[2] *= al1; lacc[3] *= al1;
        #pragma unroll
        for (int nf = 0; nf < 8; nf++) {
            oacc[nf][0] *= al0; oacc[nf][1] *= al0;
            oacc[nf][2] *= al1; oacc[nf][3] *= al1;
        }

        // ---- O += P @ V ; l += P @ ones ----
        #pragma unroll
        for (int ks = 0; ks < 8; ks++) {
            uint32_t a[4] = {ph[2 * ks][0], ph[2 * ks][1], ph[2 * ks + 1][0], ph[2 * ks + 1][1]};
            const uint32_t vk = vS + (uint32_t)(ks * 16 * RSTR);
            #pragma unroll
            for (int dt = 0; dt < 4; dt++) {
                uint32_t tmp[4];
                ldsm4t(tmp, vk + (uint32_t)(dt * 32));
                uint32_t b0[2] = {tmp[0], tmp[1]};
                uint32_t b1[2] = {tmp[2], tmp[3]};
                mma_f16(oacc[2 * dt],     a, b0);
                mma_f16(oacc[2 * dt + 1], a, b1);
            }
            mma_f16(lacc, a, bones);
        }
    }

    // ---- finalize ----
    const float inv0 = 1.f / lacc[0], inv1 = 1.f / lacc[2];
    #pragma unroll
    for (int nf = 0; nf < 8; nf++) {
        int r0 = q0 + wrow + g;
        int c  = nf * 8 + 2 * t;
        *(uint32_t*)&O[(tok0 + r0) * DIM + hoff + c]       = f2h2(oacc[nf][0] * inv0, oacc[nf][1] * inv0);
        *(uint32_t*)&O[(tok0 + r0 + 8) * DIM + hoff + c]   = f2h2(oacc[nf][2] * inv1, oacc[nf][3] * inv1);
    }
}

// ---------------- launch ----------------
extern "C" void kernel_launch(void* const* d_in, const int* in_sizes, int n_in,
                              void* d_out, int out_size)
{
    const float* x   = (const float*)d_in[0];
    const float* fc  = (const float*)d_in[1];
    const float* fs  = (const float*)d_in[2];
    const float* Wq  = (const float*)d_in[3];
    const float* Wk  = (const float*)d_in[4];
    const float* Wv  = (const float*)d_in[5];
    const float* Wo  = (const float*)d_in[6];
    const float* bo  = (const float*)d_in[7];
    float* out = (float*)d_out;

    __half *Xh, *Wh, *Qh, *Kh, *Vh, *Oh;
    cudaGetSymbolAddress((void**)&Xh, g_Xh);
    cudaGetSymbolAddress((void**)&Wh, g_Wh);
    cudaGetSymbolAddress((void**)&Qh, g_Qh);
    cudaGetSymbolAddress((void**)&Kh, g_Kh);
    cudaGetSymbolAddress((void**)&Vh, g_Vh);
    cudaGetSymbolAddress((void**)&Oh, g_Oh);

    // 0) convert inputs to half
    to_half_kernel<<<8192, 256>>>(x, Wq, Wk, Wv, Wo);

    // 1) fused QKV projections + RoPE (+QSCALE on Q) epilogue
    cudaFuncSetAttribute(gemm_h<true>,  cudaFuncAttributeMaxDynamicSharedMemorySize, G_SMEM);
    cudaFuncSetAttribute(gemm_h<false>, cudaFuncAttributeMaxDynamicSharedMemorySize, G_SMEM);
    dim3 gQKV(DIM / 128, MROWS / 128, 3);
    gemm_h<true><<<gQKV, 256, G_SMEM>>>(Xh, Wh, Qh, Kh, Vh, nullptr, nullptr, fc, fs);

    // 2) fused attention (writes half O)
    cudaFuncSetAttribute(flash_attn, cudaFuncAttributeMaxDynamicSharedMemorySize, FA_SMEM);
    dim3 gFA(SEQ / 128, BH, 1);
    flash_attn<<<gFA, 256, FA_SMEM>>>(Qh, Kh, Vh, Oh);

    // 3) out = O @ Wo^T + bo
    dim3 gOut(DIM / 128, MROWS / 128, 1);
    gemm_h<false><<<gOut, 256, G_SMEM>>>(Oh, Wh, nullptr, nullptr, nullptr, out, bo, nullptr, nullptr);
}

// round 16
// speedup vs baseline: 1.0679x; 1.0093x over previous
#include <cuda_runtime.h>
#include <cuda_fp16.h>
#include <cstdint>

// Problem constants
#define BATCH 2
#define SEQ   2048
#define DIM   1024
#define HEADS 16
#define HDIM  64
#define MROWS (BATCH * SEQ)          // 4096
#define BH    (BATCH * HEADS)        // 32

// Q projection scale: (1/sqrt(64)) * log2(e)  -> softmax done in 2^x domain
#define QSCALE 0.180336879f

// ---------------- scratch (half operand buffers) ----------------
__device__ __half g_Xh[(size_t)MROWS * DIM];
__device__ __half g_Wh[(size_t)4 * DIM * DIM];
__device__ __half g_Qh[(size_t)MROWS * DIM];
__device__ __half g_Kh[(size_t)MROWS * DIM];
__device__ __half g_Vh[(size_t)MROWS * DIM];
__device__ __half g_Oh[(size_t)MROWS * DIM];

// ---------------- helpers ----------------
__device__ __forceinline__ uint32_t f2h2(float lo, float hi) {
    __half2 h = __floats2half2_rn(lo, hi);
    return *(uint32_t*)&h;
}

__device__ __forceinline__ float ex2f(float x) {
    float y;
    asm("ex2.approx.f32 %0, %1;" : "=f"(y) : "f"(x));
    return y;
}

__device__ __forceinline__ uint32_t ex2h2(uint32_t x) {
    uint32_t y;
    asm("ex2.approx.f16x2 %0, %1;" : "=r"(y) : "r"(x));
    return y;
}

__device__ __forceinline__ void mma_f16(float c[4], const uint32_t a[4], const uint32_t b[2]) {
    asm volatile(
        "mma.sync.aligned.m16n8k16.row.col.f32.f16.f16.f32 "
        "{%0,%1,%2,%3}, {%4,%5,%6,%7}, {%8,%9}, {%0,%1,%2,%3};\n"
        : "+f"(c[0]), "+f"(c[1]), "+f"(c[2]), "+f"(c[3])
        : "r"(a[0]), "r"(a[1]), "r"(a[2]), "r"(a[3]), "r"(b[0]), "r"(b[1]));
}

__device__ __forceinline__ void ldsm4(uint32_t r[4], uint32_t addr) {
    asm volatile("ldmatrix.sync.aligned.m8n8.x4.shared.b16 {%0,%1,%2,%3}, [%4];"
        : "=r"(r[0]), "=r"(r[1]), "=r"(r[2]), "=r"(r[3]) : "r"(addr));
}

__device__ __forceinline__ void ldsm4t(uint32_t r[4], uint32_t addr) {
    asm volatile("ldmatrix.sync.aligned.m8n8.x4.trans.shared.b16 {%0,%1,%2,%3}, [%4];"
        : "=r"(r[0]), "=r"(r[1]), "=r"(r[2]), "=r"(r[3]) : "r"(addr));
}

__device__ __forceinline__ uint32_t smem_u32(const void* p) {
    uint32_t a;
    asm("{ .reg .u64 t; cvta.to.shared.u64 t, %1; cvt.u32.u64 %0, t; }" : "=r"(a) : "l"(p));
    return a;
}

#define CP_ASYNC16(dst, src) \
    asm volatile("cp.async.cg.shared.global [%0], [%1], 16;" :: "r"((uint32_t)(dst)), "l"(src) : "memory")
#define CP_COMMIT() asm volatile("cp.async.commit_group;" ::: "memory")
#define CP_WAIT(n)  asm volatile("cp.async.wait_group %0;" :: "n"(n) : "memory")

// ---------------- pre-pass: convert x and weights to half (2 float4 per thread) ----------------
__global__ void to_half_kernel(const float* __restrict__ x,
                               const float* __restrict__ wq, const float* __restrict__ wk,
                               const float* __restrict__ wv, const float* __restrict__ wo)
{
    const size_t p = (size_t)blockIdx.x * blockDim.x + threadIdx.x;   // pair index, 1M total
    const size_t i = p * 2;                                           // float4 index
    const float4* src;
    uint4* dst;
    if (i < (1u << 20)) {
        src = (const float4*)x + i;
        dst = (uint4*)((uint2*)g_Xh + i);
    } else {
        size_t j = i - (1u << 20);
        int w = (int)(j >> 18);
        const float* s = (w == 0) ? wq : ((w == 1) ? wk : ((w == 2) ? wv : wo));
        src = (const float4*)s + (j & 0x3FFFF);
        dst = (uint4*)((uint2*)g_Wh + j);
    }
    float4 v0 = src[0];
    float4 v1 = src[1];
    *dst = make_uint4(f2h2(v0.x, v0.y), f2h2(v0.z, v0.w),
                      f2h2(v1.x, v1.y), f2h2(v1.z, v1.w));
}

// ---------------- fp16 ldmatrix + cp.async GEMM, 3-stage pipeline (R13/R15 config) ----------------
#define RSTR   144                    // row stride bytes (64 halfs + 8 pad)
#define OPB    (128 * RSTR)           // bytes per operand per stage = 18432
#define STGB   (2 * OPB)              // bytes per stage             = 36864
#define G_SMEM (3 * STGB)             // 110592

template<bool QKV>
__global__ void __launch_bounds__(256, 2)
gemm_h(const __half* __restrict__ A, const __half* __restrict__ W,
       __half* __restrict__ C0h, __half* __restrict__ C1h, __half* __restrict__ C2h,
       float* __restrict__ Cf, const float* __restrict__ bias,
       const float* __restrict__ cosb, const float* __restrict__ sinb)
{
    extern __shared__ __align__(16) char sm[];
    const uint32_t sb = smem_u32(sm);

    const int z = blockIdx.z;
    const __half* B = W + ((size_t)(QKV ? z : 3) << 20);

    const int m0 = blockIdx.y * 128;
    const int n0 = blockIdx.x * 128;

    const int tid  = threadIdx.x;
    const int warp = tid >> 5;
    const int lane = tid & 31;
    const int g    = lane >> 2;
    const int t    = lane & 3;
    const int wm   = warp >> 2;          // 0..1
    const int wn   = warp & 3;           // 0..3

    int crow[4], cch[4];
    #pragma unroll
    for (int j = 0; j < 4; j++) {
        int id = tid + 256 * j;          // 0..1023
        crow[j] = id >> 3;
        cch[j]  = id & 7;
    }

    const uint32_t aBase = sb + (uint32_t)((wm * 64 + ((lane >> 3) & 1) * 8 + (lane & 7)) * RSTR
                                           + (lane >> 4) * 16);
    const uint32_t bBase = sb + (uint32_t)OPB
                         + (uint32_t)((wn * 32 + ((lane >> 4) & 1) * 8 + (lane & 7)) * RSTR
                                      + ((lane >> 3) & 1) * 16);

    float acc[4][4][4] = {};

    const int NIT = DIM / 64;   // 16

    auto fill = [&](int tt, int st) {
        if (tt < NIT) {
            const int k0 = tt * 64;
            const uint32_t stA = sb + (uint32_t)(st * STGB);
            const uint32_t stB = stA + (uint32_t)OPB;
            #pragma unroll
            for (int j = 0; j < 4; j++) {
                CP_ASYNC16(stA + (uint32_t)(crow[j] * RSTR + cch[j] * 16),
                           &A[(size_t)(m0 + crow[j]) * DIM + k0 + cch[j] * 8]);
                CP_ASYNC16(stB + (uint32_t)(crow[j] * RSTR + cch[j] * 16),
                           &B[(size_t)(n0 + crow[j]) * DIM + k0 + cch[j] * 8]);
            }
        }
        CP_COMMIT();
    };

    fill(0, 0);
    fill(1, 1);

    int s = 0;
    #pragma unroll 1
    for (int it = 0; it < NIT; it++) {
        CP_WAIT(1);
        __syncthreads();
        {
            int s2 = s + 2; if (s2 >= 3) s2 -= 3;
            fill(it + 2, s2);
        }

        const uint32_t sOff = (uint32_t)(s * STGB);
        const uint32_t aS = aBase + sOff;
        const uint32_t bS = bBase + sOff;

        #pragma unroll
        for (int ks = 0; ks < 4; ks++) {
            uint32_t af[4][4];
            #pragma unroll
            for (int mf = 0; mf < 4; mf++)
                ldsm4(af[mf], aS + (uint32_t)(mf * 16 * RSTR + ks * 32));
            uint32_t bf[4][2];
            #pragma unroll
            for (int p = 0; p < 2; p++) {
                uint32_t tmp[4];
                ldsm4(tmp, bS + (uint32_t)(p * 16 * RSTR + ks * 32));
                bf[2 * p][0]     = tmp[0]; bf[2 * p][1]     = tmp[1];
                bf[2 * p + 1][0] = tmp[2]; bf[2 * p + 1][1] = tmp[3];
            }
            #pragma unroll
            for (int mf = 0; mf < 4; mf++)
                #pragma unroll
                for (int nf = 0; nf < 4; nf++)
                    mma_f16(acc[mf][nf], af[mf], bf[nf]);
        }
        s = (s == 2) ? 0 : s + 1;
    }

    // epilogue
    #pragma unroll
    for (int mf = 0; mf < 4; mf++) {
        #pragma unroll
        for (int nf = 0; nf < 4; nf++) {
            int r = m0 + wm * 64 + mf * 16 + g;
            int c = n0 + wn * 32 + nf * 8 + 2 * t;
            float v00 = acc[mf][nf][0], v01 = acc[mf][nf][1];
            float v10 = acc[mf][nf][2], v11 = acc[mf][nf][3];
            if (QKV) {
                __half* C = (z == 0) ? C0h : ((z == 1) ? C1h : C2h);
                if (z < 2) {   // RoPE on Q,K; fold (1/8)*log2e scale into Q
                    int i  = (c & 63) >> 1;
                    int nA = r & 2047, nB = (r + 8) & 2047;
                    float cA = cosb[nA * 32 + i], sA = sinb[nA * 32 + i];
                    float cB = cosb[nB * 32 + i], sB = sinb[nB * 32 + i];
                    float o00 = v00 * cA - v01 * sA, o01 = v00 * sA + v01 * cA;
                    float o10 = v10 * cB - v11 * sB, o11 = v10 * sB + v11 * cB;
                    if (z == 0) { o00 *= QSCALE; o01 *= QSCALE; o10 *= QSCALE; o11 *= QSCALE; }
                    v00 = o00; v01 = o01; v10 = o10; v11 = o11;
                }
                *(uint32_t*)&C[(size_t)r       * DIM + c] = f2h2(v00, v01);
                *(uint32_t*)&C[(size_t)(r + 8) * DIM + c] = f2h2(v10, v11);
            } else {
                float b0 = bias[c], b1 = bias[c + 1];
                *(float2*)&Cf[(size_t)r       * DIM + c] = make_float2(v00 + b0, v01 + b1);
                *(float2*)&Cf[(size_t)(r + 8) * DIM + c] = make_float2(v10 + b0, v11 + b1);
            }
        }
    }
}

// ---------------- fp16 fused flash attention, double-buffered K/V ----------------
// Softmax in 2^x domain; exp via ex2.approx.f16x2 on pre-packed (s-m) pairs;
// l via ones-mma; next-K/V prefetch after the S-phase LDSM burst.
#define FA_OPB  18432
#define FA_Q    0
#define FA_KV   18432
#define FA_STG  36864
#define FA_SMEM (18432 + 2 * 36864)   // 92160

__global__ void __launch_bounds__(256, 2)
flash_attn(const __half* __restrict__ Q, const __half* __restrict__ K,
           const __half* __restrict__ V, __half* __restrict__ O)
{
    extern __shared__ __align__(16) char sm[];
    const uint32_t sb = smem_u32(sm);

    const int bh = blockIdx.y;
    const int b  = bh >> 4;
    const int h  = bh & 15;
    const int q0 = blockIdx.x * 128;

    const int tid  = threadIdx.x;
    const int warp = tid >> 5;
    const int lane = tid & 31;
    const int g    = lane >> 2;
    const int t    = lane & 3;
    const int wrow = warp * 16;

    const size_t hoff = (size_t)h * HDIM;
    const size_t tok0 = (size_t)b * SEQ;

    int crow[4], cch[4];
    #pragma unroll
    for (int j = 0; j < 4; j++) {
        int id = tid + 256 * j;
        crow[j] = id >> 3;
        cch[j]  = id & 7;
    }

    const uint32_t qAddr = sb + FA_Q + (uint32_t)((wrow + ((lane >> 3) & 1) * 8 + (lane & 7)) * RSTR
                                                  + (lane >> 4) * 16);
    const uint32_t kBase = sb + FA_KV + (uint32_t)((((lane >> 4) & 1) * 8 + (lane & 7)) * RSTR
                                                   + ((lane >> 3) & 1) * 16);
    const uint32_t vBase = sb + FA_KV + (uint32_t)FA_OPB
                         + (uint32_t)((((lane >> 3) & 1) * 8 + (lane & 7)) * RSTR
                                      + ((lane >> 4) & 1) * 16);

    auto fillKV = [&](int jt, int st) {
        const int j0 = jt * 128;
        const uint32_t stK = sb + FA_KV + (uint32_t)(st * FA_STG);
        const uint32_t stV = stK + (uint32_t)FA_OPB;
        #pragma unroll
        for (int j = 0; j < 4; j++) {
            CP_ASYNC16(stK + (uint32_t)(crow[j] * RSTR + cch[j] * 16),
                       &K[(tok0 + j0 + crow[j]) * DIM + hoff + cch[j] * 8]);
            CP_ASYNC16(stV + (uint32_t)(crow[j] * RSTR + cch[j] * 16),
                       &V[(tok0 + j0 + crow[j]) * DIM + hoff + cch[j] * 8]);
        }
        CP_COMMIT();
    };

    // prologue
    #pragma unroll
    for (int j = 0; j < 4; j++)
        CP_ASYNC16(sb + FA_Q + (uint32_t)(crow[j] * RSTR + cch[j] * 16),
                   &Q[(tok0 + q0 + crow[j]) * DIM + hoff + cch[j] * 8]);
    CP_COMMIT();
    fillKV(0, 0);

    float m0 = -1e30f, m1 = -1e30f;
    float oacc[8][4] = {};
    float lacc[4] = {};              // l via ones-column mma: lacc[0]=l0 rows, lacc[2]=l1 rows
    const uint32_t bones[2] = {0x3C003C00u, 0x3C003C00u};   // all-ones fp16 B fragment
    uint32_t qf[4][4];

    #pragma unroll 1
    for (int it = 0; it < SEQ / 128; it++) {
        CP_WAIT(0);
        __syncthreads();
        if (it == 0) {
            #pragma unroll
            for (int ks = 0; ks < 4; ks++)
                ldsm4(qf[ks], qAddr + (uint32_t)(ks * 32));
        }

        const uint32_t sOff = (uint32_t)((it & 1) * FA_STG);
        const uint32_t kS = kBase + sOff;
        const uint32_t vS = vBase + sOff;

        // ---- S = Q @ K^T (Q pre-scaled by (1/8)*log2e) ----
        float sacc[16][4];
        #pragma unroll
        for (int nf = 0; nf < 16; nf++)
            #pragma unroll
            for (int r = 0; r < 4; r++) sacc[nf][r] = 0.f;

        #pragma unroll
        for (int ks = 0; ks < 4; ks++) {
            #pragma unroll
            for (int p = 0; p < 8; p++) {
                uint32_t tmp[4];
                ldsm4(tmp, kS + (uint32_t)(p * 16 * RSTR + ks * 32));
                uint32_t b0[2] = {tmp[0], tmp[1]};
                uint32_t b1[2] = {tmp[2], tmp[3]};
                mma_f16(sacc[2 * p],     qf[ks], b0);
                mma_f16(sacc[2 * p + 1], qf[ks], b1);
            }
        }

        // prefetch next K/V AFTER the S-phase LDSM burst; overlaps softmax + PV
        if (it + 1 < SEQ / 128)
            fillKV(it + 1, (it + 1) & 1);

        // ---- online softmax (2^x domain) ----
        float tm0 = -1e30f, tm1 = -1e30f;
        #pragma unroll
        for (int nf = 0; nf < 16; nf++) {
            tm0 = fmaxf(tm0, fmaxf(sacc[nf][0], sacc[nf][1]));
            tm1 = fmaxf(tm1, fmaxf(sacc[nf][2], sacc[nf][3]));
        }
        tm0 = fmaxf(tm0, __shfl_xor_sync(0xffffffffu, tm0, 1));
        tm0 = fmaxf(tm0, __shfl_xor_sync(0xffffffffu, tm0, 2));
        tm1 = fmaxf(tm1, __shfl_xor_sync(0xffffffffu, tm1, 1));
        tm1 = fmaxf(tm1, __shfl_xor_sync(0xffffffffu, tm1, 2));

        float nm0 = fmaxf(m0, tm0), nm1 = fmaxf(m1, tm1);
        float al0 = ex2f(m0 - nm0), al1 = ex2f(m1 - nm1);
        m0 = nm0; m1 = nm1;

        // P = 2^(s-m): pack (s-m) to half2, then SIMD ex2.f16x2
        uint32_t ph[16][2];
        #pragma unroll
        for (int nf = 0; nf < 16; nf++) {
            ph[nf][0] = ex2h2(f2h2(sacc[nf][0] - m0, sacc[nf][1] - m0));
            ph[nf][1] = ex2h2(f2h2(sacc[nf][2] - m1, sacc[nf][3] - m1));
        }

        lacc[0] *= al0; lacc[1] *= al0;
        lacc[2] *= al1; lacc[3] *= al1;
        #pragma unroll
        for (int nf = 0; nf < 8; nf++) {
            oacc[nf][0] *= al0; oacc[nf][1] *= al0;
            oacc[nf][2] *= al1; oacc[nf][3] *= al1;
        }

        // ---- O += P @ V ; l += P @ ones ----
        #pragma unroll
        for (int ks = 0; ks < 8; ks++) {
            uint32_t a[4] = {ph[2 * ks][0], ph[2 * ks][1], ph[2 * ks + 1][0], ph[2 * ks + 1][1]};
            const uint32_t vk = vS + (uint32_t)(ks * 16 * RSTR);
            #pragma unroll
            for (int dt = 0; dt < 4; dt++) {
                uint32_t tmp[4];
                ldsm4t(tmp, vk + (uint32_t)(dt * 32));
                uint32_t b0[2] = {tmp[0], tmp[1]};
                uint32_t b1[2] = {tmp[2], tmp[3]};
                mma_f16(oacc[2 * dt],     a, b0);
                mma_f16(oacc[2 * dt + 1], a, b1);
            }
            mma_f16(lacc, a, bones);
        }
    }

    // ---- finalize ----
    const float inv0 = 1.f / lacc[0], inv1 = 1.f / lacc[2];
    #pragma unroll
    for (int nf = 0; nf < 8; nf++) {
        int r0 = q0 + wrow + g;
        int c  = nf * 8 + 2 * t;
        *(uint32_t*)&O[(tok0 + r0) * DIM + hoff + c]       = f2h2(oacc[nf][0] * inv0, oacc[nf][1] * inv0);
        *(uint32_t*)&O[(tok0 + r0 + 8) * DIM + hoff + c]   = f2h2(oacc[nf][2] * inv1, oacc[nf][3] * inv1);
    }
}

// ---------------- launch ----------------
extern "C" void kernel_launch(void* const* d_in, const int* in_sizes, int n_in,
                              void* d_out, int out_size)
{
    const float* x   = (const float*)d_in[0];
    const float* fc  = (const float*)d_in[1];
    const float* fs  = (const float*)d_in[2];
    const float* Wq  = (const float*)d_in[3];
    const float* Wk  = (const float*)d_in[4];
    const float* Wv  = (const float*)d_in[5];
    const float* Wo  = (const float*)d_in[6];
    const float* bo  = (const float*)d_in[7];
    float* out = (float*)d_out;

    __half *Xh, *Wh, *Qh, *Kh, *Vh, *Oh;
    cudaGetSymbolAddress((void**)&Xh, g_Xh);
    cudaGetSymbolAddress((void**)&Wh, g_Wh);
    cudaGetSymbolAddress((void**)&Qh, g_Qh);
    cudaGetSymbolAddress((void**)&Kh, g_Kh);
    cudaGetSymbolAddress((void**)&Vh, g_Vh);
    cudaGetSymbolAddress((void**)&Oh, g_Oh);

    // 0) convert inputs to half (1M pairs of float4)
    to_half_kernel<<<4096, 256>>>(x, Wq, Wk, Wv, Wo);

    // 1) fused QKV projections + RoPE (+QSCALE on Q) epilogue
    cudaFuncSetAttribute(gemm_h<true>,  cudaFuncAttributeMaxDynamicSharedMemorySize, G_SMEM);
    cudaFuncSetAttribute(gemm_h<false>, cudaFuncAttributeMaxDynamicSharedMemorySize, G_SMEM);
    dim3 gQKV(DIM / 128, MROWS / 128, 3);
    gemm_h<true><<<gQKV, 256, G_SMEM>>>(Xh, Wh, Qh, Kh, Vh, nullptr, nullptr, fc, fs);

    // 2) fused attention (writes half O)
    cudaFuncSetAttribute(flash_attn, cudaFuncAttributeMaxDynamicSharedMemorySize, FA_SMEM);
    dim3 gFA(SEQ / 128, BH, 1);
    flash_attn<<<gFA, 256, FA_SMEM>>>(Qh, Kh, Vh, Oh);

    // 3) out = O @ Wo^T + bo
    dim3 gOut(DIM / 128, MROWS / 128, 1);
    gemm_h<false><<<gOut, 256, G_SMEM>>>(Oh, Wh, nullptr, nullptr, nullptr, out, bo, nullptr, nullptr);
}